// round 6
// baseline (speedup 1.0000x reference)
#include <cuda_runtime.h>
#include <cuda_bf16.h>
#include <cstdint>

// Dims: B=4, C_IN=64, C_OUT=128, H=W=256, HO=WO=128, K=3 (9 taps), K_OFF=7

// ---------------- scratch ----------------
__device__ float g_offp[4 * 4 * 18 * 128 * 128];   // offset-conv channel-chunk partials
__device__ float g_wtA[16 * 128 * 44];             // A tiles: [group][m][44] (36 taps + pad)
__device__ float g_psum[512 * 16];
__device__ float g_psq[512 * 16];
__device__ float g_diag[4 * 128 * 128 * 128];      // diagnostic duplicate output (33.5 MB)

// ---------------- helpers ----------------
__device__ __forceinline__ uint32_t smem_u32(const void* p) {
    uint32_t a;
    asm("{ .reg .u64 t; cvta.to.shared.u64 t, %1; cvt.u32.u64 %0, t; }" : "=r"(a) : "l"(p));
    return a;
}
__device__ __forceinline__ uint32_t f2tf32(float f) {
    uint32_t u;
    asm("cvt.rna.tf32.f32 %0, %1;" : "=r"(u) : "f"(f));
    return u;
}
__device__ __forceinline__ void mma_tf32(float* d, uint32_t a0, uint32_t a1,
                                         uint32_t a2, uint32_t a3,
                                         uint32_t b0, uint32_t b1) {
    asm volatile(
        "mma.sync.aligned.m16n8k8.row.col.f32.tf32.tf32.f32 "
        "{%0,%1,%2,%3}, {%4,%5,%6,%7}, {%8,%9}, {%0,%1,%2,%3};"
        : "+f"(d[0]), "+f"(d[1]), "+f"(d[2]), "+f"(d[3])
        : "r"(a0), "r"(a1), "r"(a2), "r"(a3), "r"(b0), "r"(b1));
}
__device__ __forceinline__ unsigned long long packf2(float lo, float hi) {
    unsigned long long r;
    asm("mov.b64 %0, {%1, %2};" : "=l"(r) : "f"(lo), "f"(hi));
    return r;
}
__device__ __forceinline__ void fma2(unsigned long long& acc, unsigned long long v,
                                     unsigned long long w) {
    asm("fma.rn.f32x2 %0, %1, %2, %0;" : "+l"(acc) : "l"(v), "l"(w));
}
__device__ __forceinline__ void unpackf2(unsigned long long v, float& lo, float& hi) {
    asm("mov.b64 {%0, %1}, %2;" : "=f"(lo), "=f"(hi) : "l"(v));
}

#define CPA16(dst, src, sz) \
    asm volatile("cp.async.cg.shared.global [%0], [%1], 16, %2;" :: "r"(dst), "l"(src), "r"(sz))
#define CPA_COMMIT() asm volatile("cp.async.commit_group;" ::: "memory")
#define CPA_WAIT0()  asm volatile("cp.async.wait_group 0;" ::: "memory")

// ---------------------------------------------------------------------------
// Kernel 0: A prep: g_wtA[g][m][kk] = tf32(weight[m][g*36+kk]) for kk<36 else 0
// ---------------------------------------------------------------------------
__global__ __launch_bounds__(256) void prep_wt_kernel(const float* __restrict__ weight)
{
    int idx = blockIdx.x * 256 + threadIdx.x;       // 90112 total
    if (idx >= 16 * 128 * 44) return;
    int g   = idx / 5632;
    int rem = idx - g * 5632;
    int m   = rem / 44;
    int kk  = rem - m * 44;
    float v = (kk < 36) ? weight[m * 576 + g * 36 + kk] : 0.f;
    g_wtA[idx] = __uint_as_float(f2tf32(v));
}

// ---------------------------------------------------------------------------
// Kernel 1: offset conv (K=7, s=2, p=3), channel-split x4, f32x2 packed FMA.
// ---------------------------------------------------------------------------
__global__ __launch_bounds__(256) void offset_conv_kernel(
    const float* __restrict__ x,
    const float* __restrict__ w_off)
{
    __shared__ float  te[69 * 36];
    __shared__ float  to_[69 * 36];
    __shared__ float2 ws2[2 * 441];    // [group][tap][9 oc] duplicated pairs

    const int b     = blockIdx.z & 3;
    const int chunk = blockIdx.z >> 2;
    const int ox0   = blockIdx.x * 32;
    const int oy0   = blockIdx.y * 32;
    const int tid   = threadIdx.x;
    const int og    = tid >> 7;        // oc group (0: oc 0-8, 1: oc 9-17)
    const int gt    = tid & 127;
    const int tx    = gt & 31;
    const int ty    = gt >> 5;         // 0..3

    unsigned long long acc2[36];       // [rowpair 0..3][ocpair-idx p 0..8]
#pragma unroll
    for (int i = 0; i < 36; i++) acc2[i] = 0ull;

    const int iy0 = oy0 * 2 - 3;
    const int ix0 = ox0 * 2 - 3;

    for (int c = 0; c < 16; c++) {
        const int ci = chunk * 16 + c;
        const float* xp = x + ((size_t)(b * 64 + ci) << 16);
        for (int i = tid; i < 69 * 69; i += 256) {
            int r = i / 69, col = i - r * 69;
            int iy = iy0 + r, ix = ix0 + col;
            float v = 0.f;
            if (iy >= 0 && iy < 256 && ix >= 0 && ix < 256) v = xp[iy * 256 + ix];
            float* dst = (col & 1) ? to_ : te;
            dst[r * 36 + (col >> 1)] = v;
        }
        for (int i = tid; i < 882; i += 256) {
            int gi = i / 441;
            int rm = i - gi * 441;
            int t  = rm / 9;
            int p  = rm - t * 9;
            float w = w_off[((gi * 9 + p) * 64 + ci) * 49 + t];
            ws2[i] = make_float2(w, w);
        }
        __syncthreads();

#pragma unroll 1
        for (int ky = 0; ky < 7; ky++) {
#pragma unroll
            for (int kx = 0; kx < 7; kx++) {
                const int t = ky * 7 + kx;
                const float* tp = (kx & 1) ? to_ : te;
                const int cc = tx + (kx >> 1);
                unsigned long long vp[4];
#pragma unroll
                for (int rp = 0; rp < 4; rp++) {
                    const int rb = 16 * ty + 4 * rp + ky;
                    float v0 = tp[rb * 36 + cc];
                    float v1 = tp[(rb + 2) * 36 + cc];
                    vp[rp] = packf2(v0, v1);
                }
                const float2* wsp = &ws2[og * 441 + t * 9];
#pragma unroll
                for (int p = 0; p < 9; p++) {
                    unsigned long long wp = *(const unsigned long long*)(wsp + p);
#pragma unroll
                    for (int rp = 0; rp < 4; rp++)
                        fma2(acc2[rp * 9 + p], vp[rp], wp);
                }
            }
        }
        __syncthreads();
    }

    const int col = ox0 + tx;
#pragma unroll
    for (int p = 0; p < 9; p++) {
        const int oc = og * 9 + p;
        float* op = g_offp + ((size_t)((chunk * 4 + b) * 18 + oc) << 14);
#pragma unroll
        for (int rp = 0; rp < 4; rp++) {
            float a0, a1;
            unpackf2(acc2[rp * 9 + p], a0, a1);
            const int row = oy0 + ty * 8 + 2 * rp;
            op[row * 128 + col]       = a0;
            op[(row + 1) * 128 + col] = a1;
        }
    }
}

// ---------------------------------------------------------------------------
// Kernel 2: fused deformable gather + TF32 mma GEMM + bias + GN partials.
// ---------------------------------------------------------------------------
#define WIN_OFF    0          // 2 x 13 rows x 256 = 2 x 13312 B
#define BS_OFF     26624      // 2 x 128x41 floats = 2 x 20992 B
#define AS_OFF     68608      // 1 x 128x44 floats = 22528 B
#define MW_OFF     91136      // float4[1152] = 18432 B (reused for partials)
#define MI_OFF     109568     // int[1152] = 4608 B
#define FUSED_SMEM 114176

__global__ __launch_bounds__(256, 2) void fused_kernel(
    const float* __restrict__ x,
    const float* __restrict__ b_off,
    const float* __restrict__ bias,
    float* __restrict__ out)
{
    extern __shared__ char smem[];
    const uint32_t su = smem_u32(smem);
    const int tid = threadIdx.x;
    const int wid = tid >> 5;
    const int l   = tid & 31;
    const int bx  = blockIdx.x;
    const int b   = bx >> 7;
    const int ho  = bx & 127;
    const int yb  = 2 * ho - 6;        // 13-row window: y in [yb, yb+12]

    float4*   mw = (float4*)(smem + MW_OFF);
    int*      mi = (int*)(smem + MI_OFF);
    uint32_t* BsAll = (uint32_t*)(smem + BS_OFF);

    const float* xb = x + ((size_t)b << 22);

    // ---- prefetch window(0) + A(0) ----
    {
        for (int i = tid; i < 832; i += 256) {
            const int r = i >> 6, q = i & 63;
            const int y = yb + r;
            const int yc = min(max(y, 0), 255);
            const uint32_t sz = (y >= 0 && y < 256) ? 16u : 0u;
            CPA16(su + WIN_OFF + (i << 4), xb + yc * 256 + q * 4, sz);
        }
        for (int i = tid; i < 1408; i += 256)
            CPA16(su + AS_OFF + (uint32_t)(i * 16), g_wtA + i * 4, 16u);
        CPA_COMMIT();
    }

    // ---- zero B pad columns 36..39 in both buffers ----
    for (int i = tid; i < 1024; i += 256) {
        const int buf = i >> 9;
        const int r   = i & 511;
        const int p   = r >> 2;
        const int kk  = 36 + (r & 3);
        BsAll[buf * 5248 + p * 41 + kk] = 0u;
    }

    // ---- gather metadata: 9 taps x 128 pixels ----
    for (int i = tid; i < 1152; i += 256) {
        const int tap = i >> 7;
        const int wo  = i & 127;
        const int ky  = tap / 3;
        const int kx  = tap - ky * 3;
        const int hw  = ho * 128 + wo;

        float dy = b_off[tap * 2 + 0];
        float dx = b_off[tap * 2 + 1];
#pragma unroll
        for (int p = 0; p < 4; p++) {
            dy += g_offp[((size_t)((p * 4 + b) * 18 + tap * 2 + 0) << 14) + hw];
            dx += g_offp[((size_t)((p * 4 + b) * 18 + tap * 2 + 1) << 14) + hw];
        }
        const float yf = (float)(2 * ho - 1 + ky) + dy;
        const float xf = (float)(2 * wo - 1 + kx) + dx;
        const float y0f = floorf(yf), x0f = floorf(xf);
        const int y0 = (int)y0f, x0 = (int)x0f;
        const float wy1 = yf - y0f, wy0 = 1.f - wy1;
        const float wx1 = xf - x0f, wx0 = 1.f - wx1;

        float4 w;
        w.x = ((y0 >= 0) & (y0 < 256))         ? wy0 : 0.f;
        w.y = ((y0 + 1 >= 0) & (y0 + 1 < 256)) ? wy1 : 0.f;
        w.z = ((x0 >= 0) & (x0 < 256))         ? wx0 : 0.f;
        w.w = ((x0 + 1 >= 0) & (x0 + 1 < 256)) ? wx1 : 0.f;
        mw[i] = w;

        int wy = min(max(y0 - yb, 0), 11);
        const int x0c = min(max(x0, 0), 255);
        const int x1c = min(max(x0 + 1, 0), 255);
        mi[i] = (wy * 256 + x0c) | ((x1c - x0c) << 16);
    }

    // ---- accumulators ----
    float acc[4][4][4];
#pragma unroll
    for (int i = 0; i < 4; i++)
#pragma unroll
        for (int j = 0; j < 4; j++)
#pragma unroll
            for (int q = 0; q < 4; q++) acc[i][j][q] = 0.f;

    const int mg = wid & 1;        // m-half: rows mg*64..+63
    const int ng = wid >> 1;       // n-group: cols ng*32..+31
    const int lq = l >> 2;         // 0..7
    const int lr = l & 3;          // 0..3

    // ---- mainloop over 64 channels (16 groups of 4) ----
    for (int c = 0; c < 64; c++) {
        CPA_WAIT0();
        __syncthreads();

        if (c + 1 < 64) {
            const float* xc = xb + ((size_t)(c + 1) << 16);
            const uint32_t wdst = su + WIN_OFF + (uint32_t)(((c + 1) & 1) * 13312);
            for (int i = tid; i < 832; i += 256) {
                const int r = i >> 6, q = i & 63;
                const int y = yb + r;
                const int yc = min(max(y, 0), 255);
                const uint32_t sz = (y >= 0 && y < 256) ? 16u : 0u;
                CPA16(wdst + (i << 4), xc + yc * 256 + q * 4, sz);
            }
            if ((c & 3) == 0 && c > 0) {
                const float* asrc = g_wtA + (size_t)(c >> 2) * 5632;
                for (int i = tid; i < 1408; i += 256)
                    CPA16(su + AS_OFF + (uint32_t)(i * 16), asrc + i * 4, 16u);
            }
            CPA_COMMIT();
        }

        // gather channel c into group B buffer, columns 9*(c&3)+tap
        const float* win = (const float*)(smem + WIN_OFF + (c & 1) * 13312);
        uint32_t* Bs = BsAll + ((c >> 2) & 1) * 5248;
        const int colbase = 9 * (c & 3);
        for (int i = tid; i < 1152; i += 256) {
            const float4 w = mw[i];
            const int mm = mi[i];
            const int i00 = mm & 0xFFFF;
            const int i01 = i00 + (mm >> 16);
            const float top = w.z * win[i00]       + w.w * win[i01];
            const float bot = w.z * win[i00 + 256] + w.w * win[i01 + 256];
            const int wo  = i & 127;
            const int tap = i >> 7;
            Bs[wo * 41 + colbase + tap] = f2tf32(w.x * top + w.y * bot);
        }

        if ((c & 3) == 3) {
            __syncthreads();
            const uint32_t* As = (const uint32_t*)(smem + AS_OFF);
#pragma unroll
            for (int ks = 0; ks < 5; ks++) {
                const int k0 = ks * 8;
                uint32_t a0[4], a1[4], a2[4], a3[4], b0[4], b1[4];
#pragma unroll
                for (int mt = 0; mt < 4; mt++) {
                    const int row = mg * 64 + mt * 16 + lq;
                    a0[mt] = As[row * 44 + k0 + lr];
                    a1[mt] = As[(row + 8) * 44 + k0 + lr];
                    a2[mt] = As[row * 44 + k0 + 4 + lr];
                    a3[mt] = As[(row + 8) * 44 + k0 + 4 + lr];
                }
#pragma unroll
                for (int nt = 0; nt < 4; nt++) {
                    const int nr = ng * 32 + nt * 8 + lq;
                    b0[nt] = Bs[nr * 41 + k0 + lr];
                    b1[nt] = Bs[nr * 41 + k0 + 4 + lr];
                }
#pragma unroll
                for (int mt = 0; mt < 4; mt++)
#pragma unroll
                    for (int nt = 0; nt < 4; nt++)
                        mma_tf32(acc[mt][nt], a0[mt], a1[mt], a2[mt], a3[mt],
                                 b0[nt], b1[nt]);
            }
        }
    }

    // ---- epilogue: bias, store, GN partials ----
    __syncthreads();
    float* ps = (float*)(smem + MW_OFF);
    float* pq = ps + 64;

#pragma unroll
    for (int mt = 0; mt < 4; mt++) {
        const int m0 = mg * 64 + mt * 16 + lq;
        const float bv0 = bias[m0];
        const float bv1 = bias[m0 + 8];
        float s0 = 0.f, q0 = 0.f, s1 = 0.f, q1 = 0.f;
#pragma unroll
        for (int nt = 0; nt < 4; nt++) {
            const int col = ng * 32 + nt * 8 + 2 * lr;
            float v0 = acc[mt][nt][0] + bv0;
            float v1 = acc[mt][nt][1] + bv0;
            float v2 = acc[mt][nt][2] + bv1;
            float v3 = acc[mt][nt][3] + bv1;
            s0 += v0 + v1; q0 += v0 * v0 + v1 * v1;
            s1 += v2 + v3; q1 += v2 * v2 + v3 * v3;
            *(float2*)(out + (((size_t)(b * 128 + m0)) << 14) + ho * 128 + col)
                = make_float2(v0, v1);
            *(float2*)(out + (((size_t)(b * 128 + m0 + 8)) << 14) + ho * 128 + col)
                = make_float2(v2, v3);
        }
#pragma unroll
        for (int off = 16; off > 0; off >>= 1) {
            s0 += __shfl_xor_sync(0xffffffffu, s0, off);
            q0 += __shfl_xor_sync(0xffffffffu, q0, off);
            s1 += __shfl_xor_sync(0xffffffffu, s1, off);
            q1 += __shfl_xor_sync(0xffffffffu, q1, off);
        }
        if (l == 0) {
            ps[wid * 8 + mt * 2 + 0] = s0;
            pq[wid * 8 + mt * 2 + 0] = q0;
            ps[wid * 8 + mt * 2 + 1] = s1;
            pq[wid * 8 + mt * 2 + 1] = q1;
        }
    }
    __syncthreads();
    if (tid < 16) {
        const int g = tid;
        const int gm = g >> 3;
        const int slot = g & 7;
        float S = 0.f, Q = 0.f;
#pragma unroll
        for (int j = 0; j < 4; j++) {
            const int w = gm + j * 2;
            S += ps[w * 8 + slot];
            Q += pq[w * 8 + slot];
        }
        g_psum[bx * 16 + g] = S;
        g_psq [bx * 16 + g] = Q;
    }
}

// ---------------------------------------------------------------------------
// Kernel 3: GroupNorm finalize.
// ---------------------------------------------------------------------------
__global__ __launch_bounds__(256) void gn_final_kernel(
    float* __restrict__ out,
    const float* __restrict__ gamma,
    const float* __restrict__ beta)
{
    __shared__ float rs[128], rq[128];
    const int tid  = threadIdx.x;
    const int g64  = blockIdx.x >> 3;
    const int part = blockIdx.x & 7;
    const int b    = g64 >> 4;
    const int g    = g64 & 15;

    if (tid < 128) {
        rs[tid] = g_psum[(b * 128 + tid) * 16 + g];
        rq[tid] = g_psq [(b * 128 + tid) * 16 + g];
    }
    __syncthreads();
    for (int s = 64; s > 0; s >>= 1) {
        if (tid < s) { rs[tid] += rs[tid + s]; rq[tid] += rq[tid + s]; }
        __syncthreads();
    }
    const float mu   = rs[0] * (1.f / 131072.f);
    const float var  = rq[0] * (1.f / 131072.f) - mu * mu;
    const float rsig = rsqrtf(var + 1e-5f);

    const int ch = g * 8 + part;
    const float ga = gamma[ch] * rsig;
    const float be = beta[ch] - mu * ga;

    float4* p = (float4*)(out + (((size_t)(b * 128 + ch)) << 14));
    for (int i = tid; i < 4096; i += 256) {
        float4 v = p[i];
        v.x = v.x * ga + be; v.y = v.y * ga + be;
        v.z = v.z * ga + be; v.w = v.w * ga + be;
        p[i] = v;
    }
}

// ---------------------------------------------------------------------------
extern "C" void kernel_launch(void* const* d_in, const int* in_sizes, int n_in,
                              void* d_out, int out_size)
{
    const float* x      = (const float*)d_in[0];
    const float* w_off  = (const float*)d_in[1];
    const float* b_off  = (const float*)d_in[2];
    const float* weight = (const float*)d_in[3];
    const float* bias   = (const float*)d_in[4];
    const float* gamma  = (const float*)d_in[5];
    const float* beta   = (const float*)d_in[6];
    float* out = (float*)d_out;

    cudaFuncSetAttribute(fused_kernel,
                         cudaFuncAttributeMaxDynamicSharedMemorySize, FUSED_SMEM);

    float* diag = nullptr;
    cudaGetSymbolAddress((void**)&diag, g_diag);

    prep_wt_kernel<<<352, 256>>>(weight);
    offset_conv_kernel<<<dim3(4, 4, 16), 256>>>(x, w_off);
    fused_kernel<<<512, 256, FUSED_SMEM>>>(x, b_off, bias, out);
    gn_final_kernel<<<512, 256>>>(out, gamma, beta);
    // Diagnostic duplicate (writes scratch only): makes the fused kernel the
    // LAST launch so the profiler's last-kernel capture shows it, and the
    // wallclock delta vs. round 5 measures the fused kernel's duration.
    fused_kernel<<<512, 256, FUSED_SMEM>>>(x, b_off, bias, diag);
}

// round 8
// speedup vs baseline: 2.0303x; 2.0303x over previous
#include <cuda_runtime.h>
#include <cuda_bf16.h>
#include <cstdint>

// Dims: B=4, C_IN=64, C_OUT=128, H=W=256, HO=WO=128, K=3 (9 taps), K_OFF=7

// ---------------- scratch ----------------
__device__ float g_offp[4 * 18 * 128 * 128];       // offset conv output (full)
__device__ float g_wtA[16 * 128 * 44];             // deform A tiles: [group][m][44]
__device__ float g_wtB[64 * 7 * 8 * 24];           // offset weights: [ch][ky][kx8][oc24]
__device__ float g_psum[512 * 16];
__device__ float g_psq[512 * 16];

// ---------------- helpers ----------------
__device__ __forceinline__ uint32_t smem_u32(const void* p) {
    uint32_t a;
    asm("{ .reg .u64 t; cvta.to.shared.u64 t, %1; cvt.u32.u64 %0, t; }" : "=r"(a) : "l"(p));
    return a;
}
__device__ __forceinline__ uint32_t f2tf32(float f) {
    uint32_t u;
    asm("cvt.rna.tf32.f32 %0, %1;" : "=r"(u) : "f"(f));
    return u;
}
__device__ __forceinline__ void mma_tf32(float* d, uint32_t a0, uint32_t a1,
                                         uint32_t a2, uint32_t a3,
                                         uint32_t b0, uint32_t b1) {
    asm volatile(
        "mma.sync.aligned.m16n8k8.row.col.f32.tf32.tf32.f32 "
        "{%0,%1,%2,%3}, {%4,%5,%6,%7}, {%8,%9}, {%0,%1,%2,%3};"
        : "+f"(d[0]), "+f"(d[1]), "+f"(d[2]), "+f"(d[3])
        : "r"(a0), "r"(a1), "r"(a2), "r"(a3), "r"(b0), "r"(b1));
}

#define CPA16(dst, src, sz) \
    asm volatile("cp.async.cg.shared.global [%0], [%1], 16, %2;" :: "r"(dst), "l"(src), "r"(sz))
#define CPA_COMMIT() asm volatile("cp.async.commit_group;" ::: "memory")
#define CPA_WAIT0()  asm volatile("cp.async.wait_group 0;" ::: "memory")

// ---------------------------------------------------------------------------
// Kernel 0a: deform-conv A prep
// ---------------------------------------------------------------------------
__global__ __launch_bounds__(256) void prep_wt_kernel(const float* __restrict__ weight)
{
    int idx = blockIdx.x * 256 + threadIdx.x;
    if (idx >= 16 * 128 * 44) return;
    int g   = idx / 5632;
    int rem = idx - g * 5632;
    int m   = rem / 44;
    int kk  = rem - m * 44;
    float v = (kk < 36) ? weight[m * 576 + g * 36 + kk] : 0.f;
    g_wtA[idx] = __uint_as_float(f2tf32(v));
}

// ---------------------------------------------------------------------------
// Kernel 0b: offset-conv weight prep: g_wtB[c][ky][kx(8)][oc(24)]
// ---------------------------------------------------------------------------
__global__ __launch_bounds__(256) void prep_wtB_kernel(const float* __restrict__ w_off)
{
    int idx = blockIdx.x * 256 + threadIdx.x;       // 86016 total
    if (idx >= 64 * 1344) return;
    int c  = idx / 1344;
    int r  = idx - c * 1344;
    int ky = r / 192;
    int r2 = r - ky * 192;
    int kx = r2 / 24;
    int oc = r2 - kx * 24;
    float v = (kx < 7 && oc < 18) ? w_off[(oc * 64 + c) * 49 + ky * 7 + kx] : 0.f;
    g_wtB[idx] = __uint_as_float(f2tf32(v));
}

// ---------------------------------------------------------------------------
// Kernel 1: offset conv via TF32 mma. Block = one (b,ho) row.
// GEMM: M=128 px, N=24 (18 oc + pad), K = 64ch x 7ky x 8kx (kx7 zero).
// A fragments read DIRECTLY from the padded x-window (no im2col).
// SINGLE shared array; window & weight offsets derived from one base
// (R7 crashed because two __shared__ arrays were aliased via raw offsets).
// smem float layout:
//   [0, 3808)     : 2 window buffers, each 7 rows x 272 cols (col = x+4)
//   [3808, 6496)  : 2 weight buffers, each 1344 floats ([ky][kx8][oc24])
// ---------------------------------------------------------------------------
#define OCW 272
#define WT_F 3808
__global__ __launch_bounds__(256) void offset_mma_kernel(const float* __restrict__ x)
{
    __shared__ float sm[6496];

    const int tid = threadIdx.x;
    const int wid = tid >> 5;
    const int l   = tid & 31;
    const int lq  = l >> 2;
    const int lr  = l & 3;
    const int bx  = blockIdx.x;
    const int b   = bx >> 7;
    const int ho  = bx & 127;
    const int y0  = 2 * ho - 3;
    const uint32_t su = smem_u32(sm);

    const float* xb = x + ((size_t)b << 22);

    // zero pad columns (x<0 / x>255): cols 0..3 and 260..271, both buffers
    for (int i = tid; i < 2 * 7 * 16; i += 256) {
        const int buf = i >= 112;
        const int r   = i - buf * 112;
        const int row = r >> 4;
        const int k   = r & 15;
        const int col = (k < 4) ? k : 256 + k;
        sm[buf * 1904 + row * OCW + col] = 0.f;
    }

    // prefetch channel 0 (window rows + weights)
    {
        for (int i = tid; i < 448; i += 256) {
            const int r = i >> 6, q = i & 63;
            const int y = y0 + r;
            const int yc = min(max(y, 0), 255);
            const uint32_t sz = (y >= 0 && y < 256) ? 16u : 0u;
            CPA16(su + (uint32_t)(r * OCW * 4 + 16 + q * 16), xb + yc * 256 + q * 4, sz);
        }
        for (int i = tid; i < 336; i += 256)
            CPA16(su + (uint32_t)(WT_F * 4 + i * 16), g_wtB + i * 4, 16u);
        CPA_COMMIT();
    }

    float acc[3][4];
#pragma unroll
    for (int n = 0; n < 3; n++)
#pragma unroll
        for (int q = 0; q < 4; q++) acc[n][q] = 0.f;

    const int px2 = 2 * (16 * wid + lq) + 1;   // window col base: 2*px - 3 + 4

    for (int c = 0; c < 64; c++) {
        CPA_WAIT0();
        __syncthreads();

        if (c + 1 < 64) {
            const int nb = (c + 1) & 1;
            const float* xc = xb + ((size_t)(c + 1) << 16);
            for (int i = tid; i < 448; i += 256) {
                const int r = i >> 6, q = i & 63;
                const int y = y0 + r;
                const int yc = min(max(y, 0), 255);
                const uint32_t sz = (y >= 0 && y < 256) ? 16u : 0u;
                CPA16(su + (uint32_t)(nb * 1904 * 4 + r * OCW * 4 + 16 + q * 16),
                      xc + yc * 256 + q * 4, sz);
            }
            const float* wsrc = g_wtB + (size_t)(c + 1) * 1344;
            for (int i = tid; i < 336; i += 256)
                CPA16(su + (uint32_t)(WT_F * 4 + nb * 5376 + i * 16),
                      wsrc + i * 4, 16u);
            CPA_COMMIT();
        }

        const float* W  = sm + (c & 1) * 1904;
        const float* Bw = sm + WT_F + (c & 1) * 1344;
#pragma unroll
        for (int ky = 0; ky < 7; ky++) {
            const float* wr = W + ky * OCW;
            const uint32_t a0 = f2tf32(wr[px2 + lr]);
            const uint32_t a1 = f2tf32(wr[px2 + 16 + lr]);
            const uint32_t a2 = f2tf32(wr[px2 + 4 + lr]);
            const uint32_t a3 = f2tf32(wr[px2 + 20 + lr]);
            const float* bb = Bw + ky * 192;
#pragma unroll
            for (int nt = 0; nt < 3; nt++) {
                const uint32_t b0 = __float_as_uint(bb[lr * 24 + nt * 8 + lq]);
                const uint32_t b1 = __float_as_uint(bb[(lr + 4) * 24 + nt * 8 + lq]);
                mma_tf32(acc[nt], a0, a1, a2, a3, b0, b1);
            }
        }
    }

    // store: D[px][oc]; lane holds (px=16w+lq, oc=nt*8+2lr) quads
    const int px = 16 * wid + lq;
#pragma unroll
    for (int nt = 0; nt < 3; nt++) {
        const int oc0 = nt * 8 + 2 * lr;
        if (oc0 < 18) {
            float* op = g_offp + (((size_t)(b * 18 + oc0)) << 14) + ho * 128;
            op[px]     = acc[nt][0];
            op[px + 8] = acc[nt][2];
        }
        if (oc0 + 1 < 18) {
            float* op = g_offp + (((size_t)(b * 18 + oc0 + 1)) << 14) + ho * 128;
            op[px]     = acc[nt][1];
            op[px + 8] = acc[nt][3];
        }
    }
}

// ---------------------------------------------------------------------------
// Kernel 2: fused deformable gather + TF32 mma GEMM + bias + GN partials.
// ---------------------------------------------------------------------------
#define WIN_OFF    0
#define BS_OFF     26624
#define AS_OFF     68608
#define MW_OFF     91136
#define MI_OFF     109568
#define FUSED_SMEM 114176

__global__ __launch_bounds__(256, 2) void fused_kernel(
    const float* __restrict__ x,
    const float* __restrict__ b_off,
    const float* __restrict__ bias,
    float* __restrict__ out)
{
    extern __shared__ char smem[];
    const uint32_t su = smem_u32(smem);
    const int tid = threadIdx.x;
    const int wid = tid >> 5;
    const int l   = tid & 31;
    const int bx  = blockIdx.x;
    const int b   = bx >> 7;
    const int ho  = bx & 127;
    const int yb  = 2 * ho - 6;

    float4*   mw = (float4*)(smem + MW_OFF);
    int*      mi = (int*)(smem + MI_OFF);
    uint32_t* BsAll = (uint32_t*)(smem + BS_OFF);

    const float* xb = x + ((size_t)b << 22);

    {
        for (int i = tid; i < 832; i += 256) {
            const int r = i >> 6, q = i & 63;
            const int y = yb + r;
            const int yc = min(max(y, 0), 255);
            const uint32_t sz = (y >= 0 && y < 256) ? 16u : 0u;
            CPA16(su + WIN_OFF + (i << 4), xb + yc * 256 + q * 4, sz);
        }
        for (int i = tid; i < 1408; i += 256)
            CPA16(su + AS_OFF + (uint32_t)(i * 16), g_wtA + i * 4, 16u);
        CPA_COMMIT();
    }

    for (int i = tid; i < 1024; i += 256) {
        const int buf = i >> 9;
        const int r   = i & 511;
        const int p   = r >> 2;
        const int kk  = 36 + (r & 3);
        BsAll[buf * 5248 + p * 41 + kk] = 0u;
    }

    for (int i = tid; i < 1152; i += 256) {
        const int tap = i >> 7;
        const int wo  = i & 127;
        const int ky  = tap / 3;
        const int kx  = tap - ky * 3;
        const int hw  = ho * 128 + wo;

        const float dy = b_off[tap * 2 + 0]
            + g_offp[(((size_t)(b * 18 + tap * 2 + 0)) << 14) + hw];
        const float dx = b_off[tap * 2 + 1]
            + g_offp[(((size_t)(b * 18 + tap * 2 + 1)) << 14) + hw];

        const float yf = (float)(2 * ho - 1 + ky) + dy;
        const float xf = (float)(2 * wo - 1 + kx) + dx;
        const float y0f = floorf(yf), x0f = floorf(xf);
        const int y0 = (int)y0f, x0 = (int)x0f;
        const float wy1 = yf - y0f, wy0 = 1.f - wy1;
        const float wx1 = xf - x0f, wx0 = 1.f - wx1;

        float4 w;
        w.x = ((y0 >= 0) & (y0 < 256))         ? wy0 : 0.f;
        w.y = ((y0 + 1 >= 0) & (y0 + 1 < 256)) ? wy1 : 0.f;
        w.z = ((x0 >= 0) & (x0 < 256))         ? wx0 : 0.f;
        w.w = ((x0 + 1 >= 0) & (x0 + 1 < 256)) ? wx1 : 0.f;
        mw[i] = w;

        int wy = min(max(y0 - yb, 0), 11);
        const int x0c = min(max(x0, 0), 255);
        const int x1c = min(max(x0 + 1, 0), 255);
        mi[i] = (wy * 256 + x0c) | ((x1c - x0c) << 16);
    }

    float acc[4][4][4];
#pragma unroll
    for (int i = 0; i < 4; i++)
#pragma unroll
        for (int j = 0; j < 4; j++)
#pragma unroll
            for (int q = 0; q < 4; q++) acc[i][j][q] = 0.f;

    const int mg = wid & 1;
    const int ng = wid >> 1;
    const int lq = l >> 2;
    const int lr = l & 3;

    for (int c = 0; c < 64; c++) {
        CPA_WAIT0();
        __syncthreads();

        if (c + 1 < 64) {
            const float* xc = xb + ((size_t)(c + 1) << 16);
            const uint32_t wdst = su + WIN_OFF + (uint32_t)(((c + 1) & 1) * 13312);
            for (int i = tid; i < 832; i += 256) {
                const int r = i >> 6, q = i & 63;
                const int y = yb + r;
                const int yc = min(max(y, 0), 255);
                const uint32_t sz = (y >= 0 && y < 256) ? 16u : 0u;
                CPA16(wdst + (i << 4), xc + yc * 256 + q * 4, sz);
            }
            if ((c & 3) == 0 && c > 0) {
                const float* asrc = g_wtA + (size_t)(c >> 2) * 5632;
                for (int i = tid; i < 1408; i += 256)
                    CPA16(su + AS_OFF + (uint32_t)(i * 16), asrc + i * 4, 16u);
            }
            CPA_COMMIT();
        }

        const float* win = (const float*)(smem + WIN_OFF + (c & 1) * 13312);
        uint32_t* Bs = BsAll + ((c >> 2) & 1) * 5248;
        const int colbase = 9 * (c & 3);
        for (int i = tid; i < 1152; i += 256) {
            const float4 w = mw[i];
            const int mm = mi[i];
            const int i00 = mm & 0xFFFF;
            const int i01 = i00 + (mm >> 16);
            const float top = w.z * win[i00]       + w.w * win[i01];
            const float bot = w.z * win[i00 + 256] + w.w * win[i01 + 256];
            const int wo  = i & 127;
            const int tap = i >> 7;
            Bs[wo * 41 + colbase + tap] = f2tf32(w.x * top + w.y * bot);
        }

        if ((c & 3) == 3) {
            __syncthreads();
            const uint32_t* As = (const uint32_t*)(smem + AS_OFF);
#pragma unroll
            for (int ks = 0; ks < 5; ks++) {
                const int k0 = ks * 8;
                uint32_t a0[4], a1[4], a2[4], a3[4], b0[4], b1[4];
#pragma unroll
                for (int mt = 0; mt < 4; mt++) {
                    const int row = mg * 64 + mt * 16 + lq;
                    a0[mt] = As[row * 44 + k0 + lr];
                    a1[mt] = As[(row + 8) * 44 + k0 + lr];
                    a2[mt] = As[row * 44 + k0 + 4 + lr];
                    a3[mt] = As[(row + 8) * 44 + k0 + 4 + lr];
                }
#pragma unroll
                for (int nt = 0; nt < 4; nt++) {
                    const int nr = ng * 32 + nt * 8 + lq;
                    b0[nt] = Bs[nr * 41 + k0 + lr];
                    b1[nt] = Bs[nr * 41 + k0 + 4 + lr];
                }
#pragma unroll
                for (int mt = 0; mt < 4; mt++)
#pragma unroll
                    for (int nt = 0; nt < 4; nt++)
                        mma_tf32(acc[mt][nt], a0[mt], a1[mt], a2[mt], a3[mt],
                                 b0[nt], b1[nt]);
            }
        }
    }

    __syncthreads();
    float* ps = (float*)(smem + MW_OFF);
    float* pq = ps + 64;

#pragma unroll
    for (int mt = 0; mt < 4; mt++) {
        const int m0 = mg * 64 + mt * 16 + lq;
        const float bv0 = bias[m0];
        const float bv1 = bias[m0 + 8];
        float s0 = 0.f, q0 = 0.f, s1 = 0.f, q1 = 0.f;
#pragma unroll
        for (int nt = 0; nt < 4; nt++) {
            const int col = ng * 32 + nt * 8 + 2 * lr;
            float v0 = acc[mt][nt][0] + bv0;
            float v1 = acc[mt][nt][1] + bv0;
            float v2 = acc[mt][nt][2] + bv1;
            float v3 = acc[mt][nt][3] + bv1;
            s0 += v0 + v1; q0 += v0 * v0 + v1 * v1;
            s1 += v2 + v3; q1 += v2 * v2 + v3 * v3;
            *(float2*)(out + (((size_t)(b * 128 + m0)) << 14) + ho * 128 + col)
                = make_float2(v0, v1);
            *(float2*)(out + (((size_t)(b * 128 + m0 + 8)) << 14) + ho * 128 + col)
                = make_float2(v2, v3);
        }
#pragma unroll
        for (int off = 16; off > 0; off >>= 1) {
            s0 += __shfl_xor_sync(0xffffffffu, s0, off);
            q0 += __shfl_xor_sync(0xffffffffu, q0, off);
            s1 += __shfl_xor_sync(0xffffffffu, s1, off);
            q1 += __shfl_xor_sync(0xffffffffu, q1, off);
        }
        if (l == 0) {
            ps[wid * 8 + mt * 2 + 0] = s0;
            pq[wid * 8 + mt * 2 + 0] = q0;
            ps[wid * 8 + mt * 2 + 1] = s1;
            pq[wid * 8 + mt * 2 + 1] = q1;
        }
    }
    __syncthreads();
    if (tid < 16) {
        const int g = tid;
        const int gm = g >> 3;
        const int slot = g & 7;
        float S = 0.f, Q = 0.f;
#pragma unroll
        for (int j = 0; j < 4; j++) {
            const int w = gm + j * 2;
            S += ps[w * 8 + slot];
            Q += pq[w * 8 + slot];
        }
        g_psum[bx * 16 + g] = S;
        g_psq [bx * 16 + g] = Q;
    }
}

// ---------------------------------------------------------------------------
// Kernel 3: GroupNorm finalize.
// ---------------------------------------------------------------------------
__global__ __launch_bounds__(256) void gn_final_kernel(
    float* __restrict__ out,
    const float* __restrict__ gamma,
    const float* __restrict__ beta)
{
    __shared__ float rs[128], rq[128];
    const int tid  = threadIdx.x;
    const int g64  = blockIdx.x >> 3;
    const int part = blockIdx.x & 7;
    const int b    = g64 >> 4;
    const int g    = g64 & 15;

    if (tid < 128) {
        rs[tid] = g_psum[(b * 128 + tid) * 16 + g];
        rq[tid] = g_psq [(b * 128 + tid) * 16 + g];
    }
    __syncthreads();
    for (int s = 64; s > 0; s >>= 1) {
        if (tid < s) { rs[tid] += rs[tid + s]; rq[tid] += rq[tid + s]; }
        __syncthreads();
    }
    const float mu   = rs[0] * (1.f / 131072.f);
    const float var  = rq[0] * (1.f / 131072.f) - mu * mu;
    const float rsig = rsqrtf(var + 1e-5f);

    const int ch = g * 8 + part;
    const float ga = gamma[ch] * rsig;
    const float be = beta[ch] - mu * ga;

    float4* p = (float4*)(out + (((size_t)(b * 128 + ch)) << 14));
    for (int i = tid; i < 4096; i += 256) {
        float4 v = p[i];
        v.x = v.x * ga + be; v.y = v.y * ga + be;
        v.z = v.z * ga + be; v.w = v.w * ga + be;
        p[i] = v;
    }
}

// ---------------------------------------------------------------------------
extern "C" void kernel_launch(void* const* d_in, const int* in_sizes, int n_in,
                              void* d_out, int out_size)
{
    const float* x      = (const float*)d_in[0];
    const float* w_off  = (const float*)d_in[1];
    const float* b_off  = (const float*)d_in[2];
    const float* weight = (const float*)d_in[3];
    const float* bias   = (const float*)d_in[4];
    const float* gamma  = (const float*)d_in[5];
    const float* beta   = (const float*)d_in[6];
    float* out = (float*)d_out;

    cudaFuncSetAttribute(fused_kernel,
                         cudaFuncAttributeMaxDynamicSharedMemorySize, FUSED_SMEM);

    prep_wt_kernel<<<352, 256>>>(weight);
    prep_wtB_kernel<<<336, 256>>>(w_off);
    offset_mma_kernel<<<512, 256>>>(x);
    fused_kernel<<<512, 256, FUSED_SMEM>>>(x, b_off, bias, out);
    gn_final_kernel<<<512, 256>>>(out, gamma, beta);
}